// round 8
// baseline (speedup 1.0000x reference)
#include <cuda_runtime.h>

#define NB     16     // batch
#define NT     256    // timesteps
#define NIN    6
#define NHID   256
#define NFEAT  64
#define NSTATE 64
#define NMOTOR 16
#define NUNF   6
#define EPSV   1e-8f

// scratch: state-independent sensory sums  [B,T,STATE]
__device__ float g_num[NB * NT * NSTATE];
__device__ float g_den[NB * NT * NSTATE];
// per-batch producer watermark: number of completed timesteps (persists across
// replays at NT -> scan free-runs; prenet rewrites identical values: benign)
__device__ int   g_water[NB];

__device__ __forceinline__ float tanh_fast(float x) {
    float y;
    asm("tanh.approx.f32 %0, %1;" : "=f"(y) : "f"(x));
    return y;
}

__device__ __forceinline__ float fastdiv(float a, float b) {
    float r, q;
    asm("rcp.approx.f32 %0, %1;" : "=f"(r) : "f"(b));
    asm("mul.f32 %0, %1, %2;" : "=f"(q) : "f"(a), "f"(r));
    return q;
}

__device__ __forceinline__ int ld_acquire(const int* p) {
    int v;
    asm volatile("ld.acquire.gpu.b32 %0, [%1];" : "=r"(v) : "l"(p) : "memory");
    return v;
}

__device__ __forceinline__ void st_release(int* p, int v) {
    asm volatile("st.release.gpu.b32 [%0], %1;" :: "l"(p), "r"(v) : "memory");
}

// ---------------------------------------------------------------------------
// Fused kernel, 32 CTAs x 256 threads, one wave:
//   bid 0..15  : LTC scan consumer for batch b=bid (uses 128 threads)
//   bid 16..31 : sequential prenet producer for batch b=bid-16 (256 threads),
//                publishes g_water[b]=t+1 after each timestep.
// Producer runs ~0.35us/t, consumer ~1.6us/t -> prenet fully hidden.
// ---------------------------------------------------------------------------
__global__ __launch_bounds__(256, 1)
void ltc_fused(const float* __restrict__ x,
               const float* __restrict__ pw1, const float* __restrict__ pb1,
               const float* __restrict__ pw2, const float* __restrict__ pb2,
               const float* __restrict__ input_w, const float* __restrict__ input_b,
               const float* __restrict__ sw,  const float* __restrict__ smu,
               const float* __restrict__ ssig, const float* __restrict__ serev,
               const float* __restrict__ w_,    const float* __restrict__ mu_,
               const float* __restrict__ sigma_, const float* __restrict__ erev_,
               const float* __restrict__ gleak,  const float* __restrict__ vleak,
               const float* __restrict__ cm,
               const float* __restrict__ ow,     const float* __restrict__ ob,
               float* __restrict__ out)
{
    const int tid = threadIdx.x;

    if (blockIdx.x >= NB) {
        // ===================== PRENET PRODUCER (batch b) =====================
        const int b = blockIdx.x - NB;
        __shared__ float hidden[NHID];
        __shared__ float featsh[NFEAT];
        __shared__ float pn[4][NSTATE];
        __shared__ float pd[4][NSTATE];

        const int j = tid & 63;
        const int q = tid >> 6;      // 0..3

        // register-cached weights, reused for all NT timesteps
        float w1[NIN];
        #pragma unroll
        for (int k = 0; k < NIN; k++) w1[k] = pw1[k * NHID + tid];
        const float b1 = pb1[tid];
        float w2[64];
        {
            const int h0 = q * 64;
            #pragma unroll
            for (int h = 0; h < 64; h++) w2[h] = pw2[(h0 + h) * NFEAT + j];
        }

        for (int t = 0; t < NT; t++) {
            const int bt = b * NT + t;

            // phase A: hidden[h] = tanh(x . pw1[:,h] + b1), h = tid
            {
                float s = b1;
                #pragma unroll
                for (int k = 0; k < NIN; k++) s = fmaf(x[bt * NIN + k], w1[k], s);
                hidden[tid] = tanh_fast(s);
            }
            __syncthreads();

            // phase B: feat[j] partial over 64 hidden (weights in regs)
            {
                float acc = 0.0f;
                const int h0 = q * 64;
                #pragma unroll
                for (int h = 0; h < 64; h++)
                    acc = fmaf(hidden[h0 + h], w2[h], acc);
                pn[q][j] = acc;
            }
            __syncthreads();
            if (tid < NFEAT) {
                float f = pn[0][tid] + pn[1][tid] + pn[2][tid] + pn[3][tid] + pb2[tid];
                f = fmaf(f, input_w[tid], input_b[tid]);
                featsh[tid] = f;
            }
            __syncthreads();

            // phase C: sensory sums over FEAT; 4 groups of 16 feats.
            // sigmoid(z) = 0.5*tanh(0.5 z)+0.5 ; a = fma(0.5*sw, th, 0.5*sw)
            {
                float np = 0.0f, dp = 0.0f;
                const int f0 = q * 16;
                #pragma unroll
                for (int fi = 0; fi < 16; fi++) {
                    const int f   = f0 + fi;
                    const int idx = f * NSTATE + j;
                    float hswv = 0.5f * sw[idx];
                    float th = tanh_fast(0.5f * (featsh[f] - smu[idx]) * ssig[idx]);
                    float a  = fmaf(hswv, th, hswv);
                    np = fmaf(a, serev[idx], np);
                    dp += a;
                }
                pn[q][j] = np;
                pd[q][j] = dp;
            }
            __syncthreads();
            if (tid < NSTATE) {
                g_num[bt * NSTATE + tid] = pn[0][tid] + pn[1][tid] + pn[2][tid] + pn[3][tid];
                g_den[bt * NSTATE + tid] = pd[0][tid] + pd[1][tid] + pd[2][tid] + pd[3][tid];
                __threadfence();   // make this thread's stores device-visible
            }
            __syncthreads();       // all stores+fences done
            if (tid == 0) st_release(&g_water[b], t + 1);
            __syncthreads();       // smem reuse next iteration
        }
        return;
    }

    // ======================= LTC SCAN CONSUMER (batch b) =====================
    if (tid >= 128) return;        // 4 warps only; exited warps drop from barriers

    __shared__ __align__(16) float vsh[2][NSTATE];

    const int b = blockIdx.x;
    const int j = tid >> 1;        // 0..63 post neuron
    const int g = tid & 1;         // 0..1 row group (32 rows each)

    // per-thread synapse constants for rows i = g*32..g*32+31, column j.
    //   arg_k = v_i * (0.5*sigma) - 0.5*mu*sigma
    //   np    = swe + sum hwe*tanh ,  dp = swv + sum hwv*tanh
    float hs[32], hb[32], hwe[32], hwv[32];
    float swe = 0.0f, swv = 0.0f;
    #pragma unroll
    for (int k = 0; k < 32; k++) {
        const int i   = g * 32 + k;
        const int idx = i * NSTATE + j;
        float wv  = w_[idx];
        float er  = erev_[idx];
        float sgv = sigma_[idx];
        float muv = mu_[idx];
        hwv[k] = 0.5f * wv;
        hwe[k] = 0.5f * wv * er;
        hs[k]  = 0.5f * sgv;
        hb[k]  = 0.5f * muv * sgv;
        swe += hwe[k];
        swv += hwv[k];
    }

    const float cm_t = cm[j] * (float)NUNF;
    const float gl   = gleak[j];
    const float leak = gl * vleak[j];
    const float denc = cm_t + gl + EPSV;
    float owv = 0.0f, obv = 0.0f;
    if (j < NMOTOR) { owv = ow[j]; obv = ob[j]; }

    if (tid < NSTATE) vsh[0][tid] = 0.0f;
    float vj = 0.0f;
    __syncthreads();

    const float* nb   = g_num + b * NT * NSTATE;
    const float* db   = g_den + b * NT * NSTATE;
    float*       outb = out   + b * NT * NMOTOR;

    // watermark cache: poll only when the cached value is insufficient.
    // producer outpaces consumer ~4.5x, so real polls are rare (~4 total).
    int known = ld_acquire(&g_water[b]);
    while (known < 1) known = ld_acquire(&g_water[b]);

    float ns = nb[j];
    float ds = db[j];

    for (int t = 0; t < NT; t++) {
        const int tn = (t + 1 < NT) ? (t + 1) : t;
        if (known < tn + 1) {
            do { known = ld_acquire(&g_water[b]); } while (known < tn + 1);
        }
        float ns_next = nb[tn * NSTATE + j];
        float ds_next = db[tn * NSTATE + j];

        const float nsl = ns + leak;
        const float dsl = ds + denc;

        #pragma unroll
        for (int u = 0; u < NUNF; u++) {
            const int cur = u & 1;

            float np0 = swe, np1 = 0.f, np2 = 0.f, np3 = 0.f;
            float dp0 = swv, dp1 = 0.f, dp2 = 0.f, dp3 = 0.f;
            #pragma unroll
            for (int c = 0; c < 8; c++) {
                float4 vq = *reinterpret_cast<const float4*>(&vsh[cur][g * 32 + c * 4]);
                const int k = c * 4;
                float t0 = tanh_fast(fmaf(vq.x, hs[k + 0], -hb[k + 0]));
                float t1 = tanh_fast(fmaf(vq.y, hs[k + 1], -hb[k + 1]));
                float t2 = tanh_fast(fmaf(vq.z, hs[k + 2], -hb[k + 2]));
                float t3 = tanh_fast(fmaf(vq.w, hs[k + 3], -hb[k + 3]));
                np0 = fmaf(hwe[k + 0], t0, np0);
                np1 = fmaf(hwe[k + 1], t1, np1);
                np2 = fmaf(hwe[k + 2], t2, np2);
                np3 = fmaf(hwe[k + 3], t3, np3);
                dp0 = fmaf(hwv[k + 0], t0, dp0);
                dp1 = fmaf(hwv[k + 1], t1, dp1);
                dp2 = fmaf(hwv[k + 2], t2, dp2);
                dp3 = fmaf(hwv[k + 3], t3, dp3);
            }
            float dp = (dp0 + dp1) + (dp2 + dp3);
            float np = (np0 + np1) + (np2 + np3);

            dp += __shfl_xor_sync(0xffffffffu, dp, 1);
            np += __shfl_xor_sync(0xffffffffu, np, 1);

            float denom = dp + dsl;
            float numer = fmaf(cm_t, vj, np + nsl);
            vj = fastdiv(numer, denom);

            if (g == 0) vsh[cur ^ 1][j] = vj;
            __syncthreads();
        }

        if (j < NMOTOR && g == 0)
            outb[t * NMOTOR + j] = fmaf(vj, owv, obv);

        ns = ns_next;
        ds = ds_next;
    }
}

// ---------------------------------------------------------------------------
extern "C" void kernel_launch(void* const* d_in, const int* in_sizes, int n_in,
                              void* d_out, int out_size)
{
    const float* x        = (const float*)d_in[0];
    const float* pw1      = (const float*)d_in[1];
    const float* pb1      = (const float*)d_in[2];
    const float* pw2      = (const float*)d_in[3];
    const float* pb2      = (const float*)d_in[4];
    const float* input_w  = (const float*)d_in[5];
    const float* input_b  = (const float*)d_in[6];
    const float* sw       = (const float*)d_in[7];
    const float* smu      = (const float*)d_in[8];
    const float* ssig     = (const float*)d_in[9];
    const float* serev    = (const float*)d_in[10];
    const float* w_       = (const float*)d_in[11];
    const float* mu_      = (const float*)d_in[12];
    const float* sigma_   = (const float*)d_in[13];
    const float* erev_    = (const float*)d_in[14];
    const float* gleak    = (const float*)d_in[15];
    const float* vleak    = (const float*)d_in[16];
    const float* cm       = (const float*)d_in[17];
    const float* ow       = (const float*)d_in[18];
    const float* ob       = (const float*)d_in[19];
    float* out = (float*)d_out;

    ltc_fused<<<2 * NB, 256>>>(x, pw1, pb1, pw2, pb2, input_w, input_b,
                               sw, smu, ssig, serev,
                               w_, mu_, sigma_, erev_, gleak, vleak, cm,
                               ow, ob, out);
}

// round 11
// speedup vs baseline: 1.0777x; 1.0777x over previous
#include <cuda_runtime.h>

#define NB     16     // batch
#define NT     256    // timesteps
#define NIN    6
#define NHID   256
#define NFEAT  64
#define NSTATE 64
#define NMOTOR 16
#define NUNF   6
#define EPSV   1e-8f

// scratch: state-independent sensory sums  [B,T,STATE]
__device__ float g_num[NB * NT * NSTATE];
__device__ float g_den[NB * NT * NSTATE];

__device__ __forceinline__ float tanh_fast(float x) {
    float y;
    asm("tanh.approx.f32 %0, %1;" : "=f"(y) : "f"(x));
    return y;
}

__device__ __forceinline__ float fastdiv(float a, float b) {
    float r, q;
    asm("rcp.approx.f32 %0, %1;" : "=f"(r) : "f"(b));
    asm("mul.f32 %0, %1, %2;" : "=f"(q) : "f"(a), "f"(r));
    return q;
}

// ---------------------------------------------------------------------------
// Kernel 1: prenet producer, ONE WAVE. 128 CTAs x 512 threads.
// Each CTA = two 256-thread halves working on different batches (half h does
// b = h*8 + 0..7) at t = bid and t = bid+128: 16 sequential units per CTA,
// weights register-cached once. Phases are identical-length in both halves,
// so a single joint __syncthreads per phase is correct.
// ---------------------------------------------------------------------------
__global__ __launch_bounds__(512, 1)
void prenet_sensory(const float* __restrict__ x,
                    const float* __restrict__ pw1, const float* __restrict__ pb1,
                    const float* __restrict__ pw2, const float* __restrict__ pb2,
                    const float* __restrict__ input_w, const float* __restrict__ input_b,
                    const float* __restrict__ sw,  const float* __restrict__ smu,
                    const float* __restrict__ ssig, const float* __restrict__ serev)
{
    __shared__ float hidden[2][NHID];
    __shared__ float featsh[2][NFEAT];
    __shared__ float pn[2][4][NSTATE];
    __shared__ float pd[2][4][NSTATE];

    const int tid  = threadIdx.x;
    const int h    = tid >> 8;       // half 0/1
    const int htid = tid & 255;      // 0..255 within half
    const int j    = htid & 63;
    const int q    = htid >> 6;      // 0..3

    // register-cached weights (same for all units of this thread)
    float w1[NIN];
    #pragma unroll
    for (int k = 0; k < NIN; k++) w1[k] = pw1[k * NHID + htid];
    const float b1 = pb1[htid];
    float w2[64];
    {
        const int h0 = q * 64;
        #pragma unroll
        for (int hh = 0; hh < 64; hh++) w2[hh] = pw2[(h0 + hh) * NFEAT + j];
    }

    #pragma unroll 1
    for (int r = 0; r < 2; r++) {
        const int t = blockIdx.x + r * 128;
        #pragma unroll 1
        for (int bi = 0; bi < 8; bi++) {
            const int b  = h * 8 + bi;
            const int bt = b * NT + t;

            // phase A: hidden[htid] = tanh(x . pw1[:,htid] + b1)
            {
                float s = b1;
                #pragma unroll
                for (int k = 0; k < NIN; k++) s = fmaf(x[bt * NIN + k], w1[k], s);
                hidden[h][htid] = tanh_fast(s);
            }
            __syncthreads();

            // phase B: feat[j] partial over 64 hidden (weights in regs)
            {
                float acc = 0.0f;
                const int h0 = q * 64;
                #pragma unroll
                for (int hh = 0; hh < 64; hh++)
                    acc = fmaf(hidden[h][h0 + hh], w2[hh], acc);
                pn[h][q][j] = acc;
            }
            __syncthreads();
            if (htid < NFEAT) {
                float f = pn[h][0][htid] + pn[h][1][htid] + pn[h][2][htid]
                        + pn[h][3][htid] + pb2[htid];
                f = fmaf(f, input_w[htid], input_b[htid]);
                featsh[h][htid] = f;
            }
            __syncthreads();

            // phase C: sensory sums; sigmoid via tanh: a = fma(0.5sw, th, 0.5sw)
            {
                float np = 0.0f, dp = 0.0f;
                const int f0 = q * 16;
                #pragma unroll
                for (int fi = 0; fi < 16; fi++) {
                    const int f   = f0 + fi;
                    const int idx = f * NSTATE + j;
                    float hswv = 0.5f * sw[idx];
                    float th = tanh_fast(0.5f * (featsh[h][f] - smu[idx]) * ssig[idx]);
                    float a  = fmaf(hswv, th, hswv);
                    np = fmaf(a, serev[idx], np);
                    dp += a;
                }
                pn[h][q][j] = np;
                pd[h][q][j] = dp;
            }
            __syncthreads();
            if (htid < NSTATE) {
                g_num[bt * NSTATE + htid] = pn[h][0][htid] + pn[h][1][htid]
                                          + pn[h][2][htid] + pn[h][3][htid];
                g_den[bt * NSTATE + htid] = pd[h][0][htid] + pd[h][1][htid]
                                          + pd[h][2][htid] + pd[h][3][htid];
            }
            __syncthreads();   // protect smem reuse next unit
        }
    }
}

// ---------------------------------------------------------------------------
// Kernel 2: sequential LTC scan — proven R7 body (408us, rel_err 6.5e-6).
// One CTA per batch (16 CTAs), 128 threads (4 warps, one per SMSP).
// j = tid>>1, g = tid&1 (32 rows per thread). f32 tanh.approx only.
// One shfl level, double-buffered v, one barrier per unfold, LDG prefetch.
// ---------------------------------------------------------------------------
__global__ __launch_bounds__(128, 1)
void ltc_scan(const float* __restrict__ w_,    const float* __restrict__ mu_,
              const float* __restrict__ sigma_, const float* __restrict__ erev_,
              const float* __restrict__ gleak,  const float* __restrict__ vleak,
              const float* __restrict__ cm,
              const float* __restrict__ ow,     const float* __restrict__ ob,
              float* __restrict__ out)
{
    __shared__ __align__(16) float vsh[2][NSTATE];

    const int b   = blockIdx.x;
    const int tid = threadIdx.x;
    const int j   = tid >> 1;      // 0..63 post neuron
    const int g   = tid & 1;       // 0..1 row group (32 rows each)

    // per-thread synapse constants for rows i = g*32..g*32+31, column j.
    //   arg_k = v_i * (0.5*sigma) - 0.5*mu*sigma
    //   np    = swe + sum hwe*tanh ,  dp = swv + sum hwv*tanh
    float hs[32], hb[32], hwe[32], hwv[32];
    float swe = 0.0f, swv = 0.0f;
    #pragma unroll
    for (int k = 0; k < 32; k++) {
        const int i   = g * 32 + k;
        const int idx = i * NSTATE + j;
        float wv  = w_[idx];
        float er  = erev_[idx];
        float sgv = sigma_[idx];
        float muv = mu_[idx];
        hwv[k] = 0.5f * wv;
        hwe[k] = 0.5f * wv * er;
        hs[k]  = 0.5f * sgv;
        hb[k]  = 0.5f * muv * sgv;
        swe += hwe[k];
        swv += hwv[k];
    }

    const float cm_t = cm[j] * (float)NUNF;
    const float gl   = gleak[j];
    const float leak = gl * vleak[j];
    const float denc = cm_t + gl + EPSV;
    float owv = 0.0f, obv = 0.0f;
    if (j < NMOTOR) { owv = ow[j]; obv = ob[j]; }

    if (tid < NSTATE) vsh[0][tid] = 0.0f;
    float vj = 0.0f;
    __syncthreads();

    const float* nb   = g_num + b * NT * NSTATE;
    const float* db   = g_den + b * NT * NSTATE;
    float*       outb = out   + b * NT * NMOTOR;

    float ns = nb[j];
    float ds = db[j];

    for (int t = 0; t < NT; t++) {
        // issue next-t loads immediately; consumed only after 6 unfolds
        const int tn = (t + 1 < NT) ? (t + 1) : t;
        float ns_next = nb[tn * NSTATE + j];
        float ds_next = db[tn * NSTATE + j];

        const float nsl = ns + leak;
        const float dsl = ds + denc;

        #pragma unroll
        for (int u = 0; u < NUNF; u++) {
            const int cur = u & 1;

            float np0 = swe, np1 = 0.f, np2 = 0.f, np3 = 0.f;
            float dp0 = swv, dp1 = 0.f, dp2 = 0.f, dp3 = 0.f;
            #pragma unroll
            for (int c = 0; c < 8; c++) {
                float4 vq = *reinterpret_cast<const float4*>(&vsh[cur][g * 32 + c * 4]);
                const int k = c * 4;
                float t0 = tanh_fast(fmaf(vq.x, hs[k + 0], -hb[k + 0]));
                float t1 = tanh_fast(fmaf(vq.y, hs[k + 1], -hb[k + 1]));
                float t2 = tanh_fast(fmaf(vq.z, hs[k + 2], -hb[k + 2]));
                float t3 = tanh_fast(fmaf(vq.w, hs[k + 3], -hb[k + 3]));
                np0 = fmaf(hwe[k + 0], t0, np0);
                np1 = fmaf(hwe[k + 1], t1, np1);
                np2 = fmaf(hwe[k + 2], t2, np2);
                np3 = fmaf(hwe[k + 3], t3, np3);
                dp0 = fmaf(hwv[k + 0], t0, dp0);
                dp1 = fmaf(hwv[k + 1], t1, dp1);
                dp2 = fmaf(hwv[k + 2], t2, dp2);
                dp3 = fmaf(hwv[k + 3], t3, dp3);
            }
            float dp = (dp0 + dp1) + (dp2 + dp3);
            float np = (np0 + np1) + (np2 + np3);

            dp += __shfl_xor_sync(0xffffffffu, dp, 1);
            np += __shfl_xor_sync(0xffffffffu, np, 1);

            float denom = dp + dsl;
            float numer = fmaf(cm_t, vj, np + nsl);
            vj = fastdiv(numer, denom);

            if (g == 0) vsh[cur ^ 1][j] = vj;
            __syncthreads();
        }

        if (j < NMOTOR && g == 0)
            outb[t * NMOTOR + j] = fmaf(vj, owv, obv);

        ns = ns_next;
        ds = ds_next;
    }
}

// ---------------------------------------------------------------------------
extern "C" void kernel_launch(void* const* d_in, const int* in_sizes, int n_in,
                              void* d_out, int out_size)
{
    const float* x        = (const float*)d_in[0];
    const float* pw1      = (const float*)d_in[1];
    const float* pb1      = (const float*)d_in[2];
    const float* pw2      = (const float*)d_in[3];
    const float* pb2      = (const float*)d_in[4];
    const float* input_w  = (const float*)d_in[5];
    const float* input_b  = (const float*)d_in[6];
    const float* sw       = (const float*)d_in[7];
    const float* smu      = (const float*)d_in[8];
    const float* ssig     = (const float*)d_in[9];
    const float* serev    = (const float*)d_in[10];
    const float* w_       = (const float*)d_in[11];
    const float* mu_      = (const float*)d_in[12];
    const float* sigma_   = (const float*)d_in[13];
    const float* erev_    = (const float*)d_in[14];
    const float* gleak    = (const float*)d_in[15];
    const float* vleak    = (const float*)d_in[16];
    const float* cm       = (const float*)d_in[17];
    const float* ow       = (const float*)d_in[18];
    const float* ob       = (const float*)d_in[19];
    float* out = (float*)d_out;

    prenet_sensory<<<128, 512>>>(x, pw1, pb1, pw2, pb2, input_w, input_b,
                                 sw, smu, ssig, serev);
    ltc_scan<<<NB, 128>>>(w_, mu_, sigma_, erev_, gleak, vleak, cm, ow, ob, out);
}